// round 1
// baseline (speedup 1.0000x reference)
#include <cuda_runtime.h>

#define PI_D 3.14159265358979323846264338327950288

// ---------------- problem constants ----------------
#define BB   8
#define CC   3
#define HIN  512
#define WIN  512
#define KH   31
#define KW   31
#define PH   15
#define PW   15
#define NP   542            // padded H = W = 512 + 2*15
#define NP2  (NP*NP)        // 293764
#define NIMG (BB*CC)        // 24
#define MP   2048           // Bluestein FFT length (>= 2*542-1)
#define LOG2M 11
#define NF   8
#define FS   3

// ---------------- persistent device scratch (no allocs allowed) ----------------
__device__ float2 g_X[NIMG*NP2];     // current spatial image (real in .x)
__device__ float2 g_T[NIMG*NP2];     // scratch (between passes)
__device__ float2 g_F[NIMG*NP2];     // frequency / blurred buffer
__device__ float2 g_Dk[BB*NP2];      // OTF of blur kernel per batch
__device__ float  g_DgSum[CC*NP2];   // sum_f |Dg|^2 per channel
__device__ float2 g_Tk[BB*NP*KW];    // intermediate for Dk two-step DFT
__device__ float  g_v0[BB*NP];       // edgetaper taper vectors (rows)
__device__ float  g_v1[BB*NP];       // edgetaper taper vectors (cols)
__device__ float2 g_Bf[MP];          // FFT of Bluestein chirp sequence
__device__ float2 g_chirp[NP];       // exp(-i*pi*n^2/NP)
__device__ float2 g_w2048[MP/2];     // exp(-2*pi*i*k/2048)
__device__ float2 g_w542[NP];        // exp(-2*pi*i*m/542)

__device__ __forceinline__ float2 cmul(float2 a, float2 b) {
    return make_float2(a.x*b.x - a.y*b.y, a.x*b.y + a.y*b.x);
}

// ---------------- 2048-point Stockham radix-2 FFT in shared memory ----------------
// SIGN=+1: forward (e^{-i}), SIGN=-1: inverse direction (e^{+i}), no scaling here.
// Input in b0; returns pointer to buffer holding the (naturally ordered) result.
template<int SIGN>
__device__ float2* fft2048(float2* b0, float2* b1) {
    float2* src = b0;
    float2* dst = b1;
#pragma unroll
    for (int t = 0; t < LOG2M; ++t) {
        const int s = 1 << t;
        for (int i = threadIdx.x; i < MP/2; i += blockDim.x) {
            const int q = i & (s - 1);
            const int ps = i & ~(s - 1);        // p * s  (twiddle index)
            float2 xa = src[i];                 // q + s*p == i
            float2 xb = src[i + MP/2];          // q + s*(p+m), s*m == MP/2
            float2 w  = g_w2048[ps];
            if (SIGN < 0) w.y = -w.y;
            float2 su = make_float2(xa.x + xb.x, xa.y + xb.y);
            float2 di = make_float2(xa.x - xb.x, xa.y - xb.y);
            const int o = q + (ps << 1);
            dst[o]     = su;
            dst[o + s] = cmul(di, w);
        }
        __syncthreads();
        float2* tmp = src; src = dst; dst = tmp;
    }
    return src;
}

// ---------------- table init (runs every launch; deterministic) ----------------
__global__ void init_tables() {
    __shared__ float2 sA[MP];
    __shared__ float2 sB[MP];
    const int tid = threadIdx.x;
    for (int k = tid; k < MP/2; k += blockDim.x) {
        double a = -2.0 * PI_D * (double)k / (double)MP;
        g_w2048[k] = make_float2((float)cos(a), (float)sin(a));
    }
    for (int m = tid; m < NP; m += blockDim.x) {
        double a = -2.0 * PI_D * (double)m / (double)NP;
        g_w542[m] = make_float2((float)cos(a), (float)sin(a));
        long tq = ((long)m * (long)m) % (2L * NP);
        double ca = -PI_D * (double)tq / (double)NP;
        g_chirp[m] = make_float2((float)cos(ca), (float)sin(ca));
    }
    __syncthreads();
    for (int i = tid; i < MP; i += blockDim.x) sA[i] = make_float2(0.f, 0.f);
    __syncthreads();
    for (int n = tid; n < NP; n += blockDim.x) {
        float2 c = g_chirp[n];
        float2 b = make_float2(c.x, -c.y);      // conj(chirp) = e^{+i pi n^2/N}
        sA[n] = b;
        if (n > 0) sA[MP - n] = b;
    }
    __syncthreads();
    float2* r = fft2048<1>(sA, sB);
    for (int i = tid; i < MP; i += blockDim.x) g_Bf[i] = r[i];
}

// ---------------- edgetaper alpha vectors from kernel autocorrelation ----------------
__global__ void compute_v(const float* __restrict__ kk) {
    const int b = blockIdx.x;
    __shared__ float p0[KH], p1[KW], z0[KH], z1[KW];
    const int tid = threadIdx.x;
    const float* kb = kk + b * KH * KW;
    if (tid < KH) {
        float s = 0.f;
        for (int j = 0; j < KW; ++j) s += kb[tid*KW + j];
        p0[tid] = s;
    } else if (tid < KH + KW) {
        int j = tid - KH; float s = 0.f;
        for (int i = 0; i < KH; ++i) s += kb[i*KW + j];
        p1[j] = s;
    }
    __syncthreads();
    if (tid < KH) {
        float s = 0.f;
        for (int i = 0; i + tid < KH; ++i) s += p0[i] * p0[i + tid];
        z0[tid] = s;
    } else if (tid < KH + KW) {
        int m = tid - KH; float s = 0.f;
        for (int i = 0; i + m < KW; ++i) s += p1[i] * p1[i + m];
        z1[m] = s;
    }
    __syncthreads();
    const float inv0 = 1.f / z0[0];
    const float inv1 = 1.f / z1[0];
    for (int j = tid; j < NP; j += blockDim.x) {
        float a0, a1;
        if (j <= KH - 1)                a0 = z0[j];
        else if (j >= NP - 1)           a0 = z0[0];
        else if (j >= (NP-1)-(KH-1))    a0 = z0[(NP-1) - j];
        else                            a0 = 0.f;
        if (j <= KW - 1)                a1 = z1[j];
        else if (j >= NP - 1)           a1 = z1[0];
        else if (j >= (NP-1)-(KW-1))    a1 = z1[(NP-1) - j];
        else                            a1 = 0.f;
        g_v0[b*NP + j] = 1.f - a0 * inv0;
        g_v1[b*NP + j] = 1.f - a1 * inv1;
    }
}

// ---------------- Dk = psf2otf(k): two-step small DFT ----------------
__global__ void compute_Tk(const float* __restrict__ kk) {
    const int b = blockIdx.x, u = blockIdx.y;
    const int j = threadIdx.x;
    if (j >= KW) return;
    const float* kb = kk + b * KH * KW;
    float2 acc = make_float2(0.f, 0.f);
    for (int i = 0; i < KH; ++i) {
        int m = (u * (i - PH)) % NP; if (m < 0) m += NP;
        float2 w = g_w542[m];
        float kv = kb[i*KW + j];
        acc.x += kv * w.x;
        acc.y += kv * w.y;
    }
    g_Tk[(b*NP + u)*KW + j] = acc;
}

__global__ void compute_Dk() {
    const int u = blockIdx.x, b = blockIdx.y;
    __shared__ float2 Trow[KW];
    if (threadIdx.x < KW) Trow[threadIdx.x] = g_Tk[(b*NP + u)*KW + threadIdx.x];
    __syncthreads();
    for (int v = threadIdx.x; v < NP; v += blockDim.x) {
        float2 acc = make_float2(0.f, 0.f);
        for (int j = 0; j < KW; ++j) {
            int m = (v * (j - PW)) % NP; if (m < 0) m += NP;
            float2 w = g_w542[m];
            float2 t = Trow[j];
            acc.x += t.x*w.x - t.y*w.y;
            acc.y += t.x*w.y + t.y*w.x;
        }
        g_Dk[b*NP2 + u*NP + v] = acc;
    }
}

// ---------------- Dg_sum = sum_f |psf2otf(filters)|^2 ----------------
__global__ void compute_DgSum(const float* __restrict__ filters) {
    const int u = blockIdx.x, c = blockIdx.y;
    __shared__ float fl[NF*FS*FS];
    for (int i = threadIdx.x; i < NF*FS*FS; i += blockDim.x) {
        int f = i / (FS*FS);
        int r = i % (FS*FS);
        fl[i] = filters[(f*CC + c)*FS*FS + r];
    }
    __syncthreads();
    for (int v = threadIdx.x; v < NP; v += blockDim.x) {
        float sum = 0.f;
        for (int f = 0; f < NF; ++f) {
            float2 acc = make_float2(0.f, 0.f);
            for (int i = 0; i < FS; ++i)
                for (int j = 0; j < FS; ++j) {
                    int m = (u*(i-1) + v*(j-1)) % NP; if (m < 0) m += NP;
                    float2 w = g_w542[m];
                    float kv = fl[f*9 + i*3 + j];
                    acc.x += kv * w.x;
                    acc.y += kv * w.y;
                }
            sum += acc.x*acc.x + acc.y*acc.y;
        }
        g_DgSum[c*NP2 + u*NP + v] = sum;
    }
}

// ---------------- edge-replicate pad into complex image ----------------
__global__ void pad_edge(const float* __restrict__ y) {
    const int idx = blockIdx.x * blockDim.x + threadIdx.x;
    if (idx >= NIMG*NP2) return;
    const int w = idx % NP;
    const int h = (idx / NP) % NP;
    const int img = idx / NP2;
    const int sh = min(max(h - PH, 0), HIN - 1);
    const int sw = min(max(w - PW, 0), WIN - 1);
    g_X[idx] = make_float2(y[(size_t)img*HIN*WIN + sh*WIN + sw], 0.f);
}

// ---------------- Bluestein 542-point pass along rows, transposed write ----------------
// INV=0: forward DFT; INV=1: inverse DFT (includes 1/542 scale).
// SRC/DST select buffers: 0=g_X, 1=g_T, 2=g_F.
template<int S>
__device__ __forceinline__ float2* bufsel() {
    return (S == 0) ? g_X : ((S == 1) ? g_T : g_F);
}

template<int INV, int SRC, int DST>
__global__ void __launch_bounds__(256) fft_pass() {
    __shared__ float2 sA[MP];
    __shared__ float2 sB[MP];
    const int row = blockIdx.x;
    const int img = blockIdx.y;
    const float2* __restrict__ src = bufsel<SRC>() + ((size_t)img*NP + row)*NP;
    float2* __restrict__ dst = bufsel<DST>() + (size_t)img*NP2;

    for (int i = threadIdx.x; i < MP; i += blockDim.x) {
        float2 v = make_float2(0.f, 0.f);
        if (i < NP) {
            v = src[i];
            if (INV) v.y = -v.y;            // conj trick: inv = conj(fwd(conj(x)))/N
            v = cmul(v, g_chirp[i]);
        }
        sA[i] = v;
    }
    __syncthreads();

    float2* r  = fft2048<1>(sA, sB);
    float2* o  = (r == sA) ? sB : sA;
    for (int i = threadIdx.x; i < MP; i += blockDim.x) r[i] = cmul(r[i], g_Bf[i]);
    __syncthreads();
    float2* r2 = fft2048<-1>(r, o);

    const float sc = 1.f / (float)MP;
    for (int kk2 = threadIdx.x; kk2 < NP; kk2 += blockDim.x) {
        float2 v = cmul(r2[kk2], g_chirp[kk2]);
        v.x *= sc; v.y *= sc;
        if (INV) {
            const float s2 = 1.f / (float)NP;
            v.x *=  s2;
            v.y *= -s2;                     // conj back
        }
        dst[(size_t)kk2*NP + row] = v;      // transposed write
    }
}

// ---------------- elementwise stages ----------------
__global__ void freq_mul() {                 // F *= Dk   (OTF blur, broadcast over channel)
    const int idx = blockIdx.x * blockDim.x + threadIdx.x;
    if (idx >= NIMG*NP2) return;
    const int pix = idx % NP2;
    const int b = (idx / NP2) / CC;
    g_F[idx] = cmul(g_F[idx], g_Dk[b*NP2 + pix]);
}

__global__ void blend() {                    // X = alpha*X + (1-alpha)*blurred.real
    const int idx = blockIdx.x * blockDim.x + threadIdx.x;
    if (idx >= NIMG*NP2) return;
    const int w = idx % NP;
    const int h = (idx / NP) % NP;
    const int b = (idx / NP2) / CC;
    const float a = g_v0[b*NP + h] * g_v1[b*NP + w];
    const float xr = g_X[idx].x;
    const float br = g_F[idx].x;
    g_X[idx] = make_float2(a*xr + (1.f - a)*br, 0.f);
}

__global__ void wiener_mul(const float* __restrict__ lam) {
    const int idx = blockIdx.x * blockDim.x + threadIdx.x;
    if (idx >= NIMG*NP2) return;
    const int pix = idx % NP2;
    const int img = idx / NP2;
    const int b = img / CC;
    const int c = img % CC;
    const float el = expf(lam[0]);
    const float2 dk = g_Dk[b*NP2 + pix];
    const float om = 1.f / (dk.x*dk.x + dk.y*dk.y + el * g_DgSum[c*NP2 + pix]);
    const float2 f = g_F[idx];
    // conj(dk) * f * omega
    g_F[idx] = make_float2((dk.x*f.x + dk.y*f.y) * om,
                           (dk.x*f.y - dk.y*f.x) * om);
}

__global__ void copy_out(float* __restrict__ out) {
    const int idx = blockIdx.x * blockDim.x + threadIdx.x;
    if (idx >= NIMG*NP2) return;
    out[idx] = g_F[idx].x;
}

// ---------------- launch ----------------
extern "C" void kernel_launch(void* const* d_in, const int* in_sizes, int n_in,
                              void* d_out, int out_size) {
    const float* y       = (const float*)d_in[0];
    const float* kk      = (const float*)d_in[1];
    const float* lam     = (const float*)d_in[2];
    const float* filters = (const float*)d_in[3];
    float* out = (float*)d_out;

    init_tables<<<1, 256>>>();
    compute_v<<<BB, 64>>>(kk);
    compute_Tk<<<dim3(BB, NP), 32>>>(kk);
    compute_Dk<<<dim3(NP, BB), 256>>>();
    compute_DgSum<<<dim3(NP, CC), 256>>>(filters);

    const int n  = NIMG * NP2;
    const int tb = 256;
    const int gb = (n + tb - 1) / tb;
    pad_edge<<<gb, tb>>>(y);

    const dim3 pg(NP, NIMG);
    for (int it = 0; it < 3; ++it) {
        fft_pass<0, 0, 1><<<pg, 256>>>();   // X -> T  (row FFT, transposed)
        fft_pass<0, 1, 2><<<pg, 256>>>();   // T -> F  (col FFT, back to natural layout)
        freq_mul<<<gb, tb>>>();             // F *= OTF
        fft_pass<1, 2, 1><<<pg, 256>>>();   // F -> T  (inverse)
        fft_pass<1, 1, 2><<<pg, 256>>>();   // T -> F  (inverse) -> blurred spatial
        blend<<<gb, tb>>>();                // X = a*X + (1-a)*blurred
    }

    fft_pass<0, 0, 1><<<pg, 256>>>();       // Fy = fft2(X)
    fft_pass<0, 1, 2><<<pg, 256>>>();
    wiener_mul<<<gb, tb>>>(lam);            // F = Omega * conj(Dk) * Fy
    fft_pass<1, 2, 1><<<pg, 256>>>();       // out = ifft2(...)
    fft_pass<1, 1, 2><<<pg, 256>>>();
    copy_out<<<gb, tb>>>(out);
}

// round 4
// speedup vs baseline: 2.5774x; 2.5774x over previous
#include <cuda_runtime.h>

#define PI_D 3.14159265358979323846264338327950288

// ---------------- problem constants ----------------
#define BB   8
#define CC   3
#define HIN  512
#define WIN  512
#define KH   31
#define KW   31
#define PH   15
#define PW   15
#define NP   542            // padded H = W = 512 + 2*15
#define NP2  (NP*NP)        // 293764
#define NIMG (BB*CC)        // 24
#define MP   2048           // Bluestein FFT length (>= 2*542-1)
#define NF   8
#define FS   3

// load modes
#define LM_X     0
#define LM_BLEND 1
#define LM_C     2
#define LM_DK    3
#define LM_WI    4

// ---------------- persistent device scratch ----------------
__device__ float  g_Xr[NIMG*NP2];    // spatial image (real)
__device__ float  g_Fr[NIMG*NP2];    // blurred spatial (real)
__device__ float2 g_T[NIMG*NP2];     // intermediate (after 1st 1D pass)
__device__ float2 g_U[NIMG*NP2];     // frequency domain
__device__ float2 g_Dk[BB*NP2];      // OTF of blur kernel per batch
__device__ float  g_DgSum[CC*NP2];   // sum_f |Dg|^2 per channel
__device__ float2 g_Tk[BB*NP*KW];    // intermediate for Dk two-step DFT
__device__ float  g_v0[BB*NP];       // edgetaper taper vectors (rows)
__device__ float  g_v1[BB*NP];       // edgetaper taper vectors (cols)
__device__ float2 g_Bf[MP];          // FFT of Bluestein chirp sequence
__device__ float2 g_chirp[NP];       // exp(-i*pi*n^2/NP)
__device__ float2 g_w2048[MP/2];     // exp(-2*pi*i*k/2048)
__device__ float2 g_w542[NP];        // exp(-2*pi*i*m/542)

__device__ __forceinline__ float2 cmul(float2 a, float2 b) {
    return make_float2(a.x*b.x - a.y*b.y, a.x*b.y + a.y*b.x);
}
__device__ __forceinline__ float2 cadd(float2 a, float2 b) { return make_float2(a.x+b.x, a.y+b.y); }
__device__ __forceinline__ float2 csub(float2 a, float2 b) { return make_float2(a.x-b.x, a.y-b.y); }

// ---------------- smem swizzles (bank-conflict-free layouts) ----------------
// phi<0>: identity. phi<1>: permute k within 8-groups by (b + b>>3).
// phi<2>: permute the middle 8-slot (bits [3:6)) by +p.
template<int P>
__device__ __forceinline__ int phi(int a) {
    if (P == 0) return a;
    if (P == 1) return (a & ~7) | (((a & 7) + (a >> 3) + (a >> 6)) & 7);
    return (a & ~56) | ((((a >> 3) + (a >> 6)) & 7) << 3);
}

// ---------------- radix-4 / radix-8 butterflies ----------------
template<int SIGN>
__device__ __forceinline__ void dft4(float2& a, float2& b, float2& c, float2& d) {
    float2 s0 = cadd(a, c), s1 = csub(a, c);
    float2 s2 = cadd(b, d), s3 = csub(b, d);
    float2 s3r = (SIGN > 0) ? make_float2(s3.y, -s3.x) : make_float2(-s3.y, s3.x);
    a = cadd(s0, s2); b = cadd(s1, s3r); c = csub(s0, s2); d = csub(s1, s3r);
}

template<int SIGN>
__device__ __forceinline__ void dft8(const float2* x, float2* y) {
    float2 e0=x[0], e1=x[2], e2=x[4], e3=x[6];
    float2 o0=x[1], o1=x[3], o2=x[5], o3=x[7];
    dft4<SIGN>(e0, e1, e2, e3);
    dft4<SIGN>(o0, o1, o2, o3);
    const float rt = 0.70710678118654752440f;
    const float2 w1 = make_float2(rt,  (SIGN > 0) ? -rt : rt);
    const float2 w3 = make_float2(-rt, (SIGN > 0) ? -rt : rt);
    o1 = cmul(o1, w1);
    o2 = (SIGN > 0) ? make_float2(o2.y, -o2.x) : make_float2(-o2.y, o2.x);
    o3 = cmul(o3, w3);
    y[0]=cadd(e0,o0); y[4]=csub(e0,o0);
    y[1]=cadd(e1,o1); y[5]=csub(e1,o1);
    y[2]=cadd(e2,o2); y[6]=csub(e2,o2);
    y[3]=cadd(e3,o3); y[7]=csub(e3,o3);
}

// ---------------- Stockham radix-8 stage ----------------
template<int SIGN, int S, int PSRC, int PDST>
__device__ __forceinline__ void radix8_stage(const float2* __restrict__ src,
                                             float2* __restrict__ dst) {
    const int i = threadIdx.x;
    const int q = i & (S - 1);
    float2 x[8];
#pragma unroll
    for (int r = 0; r < 8; ++r) x[r] = src[phi<PSRC>(i + 256 * r)];
    float2 y[8];
    dft8<SIGN>(x, y);
    const int ps = i & ~(S - 1);            // p * S  (< 1024 always)
    float2 w = g_w2048[ps];
    if (SIGN < 0) w.y = -w.y;
    float2 wk = w;
#pragma unroll
    for (int k = 1; k < 8; ++k) {
        y[k] = cmul(y[k], wk);
        if (k < 7) wk = cmul(wk, w);
    }
    const int base = q + (ps << 3);         // q + 8*S*p
#pragma unroll
    for (int k = 0; k < 8; ++k) dst[phi<PDST>(base + S * k)] = y[k];
}

template<int SIGN>
__device__ __forceinline__ void radix4_stage(const float2* __restrict__ src,
                                             float2* __restrict__ dst) {
    const int i = threadIdx.x;
#pragma unroll
    for (int t = 0; t < 2; ++t) {
        const int j = i + 256 * t;          // p = 0 for all j < 512 -> no twiddles
        float2 a = src[j], b = src[j+512], c = src[j+1024], d = src[j+1536];
        dft4<SIGN>(a, b, c, d);
        dst[j] = a; dst[j+512] = b; dst[j+1024] = c; dst[j+1536] = d;
    }
}

// 2048-point FFT: input in A (identity layout), result in A (identity layout).
// Caller must __syncthreads() after filling A.
template<int SIGN>
__device__ __forceinline__ void fft2048_r8(float2* A, float2* B) {
    radix8_stage<SIGN,  1, 0, 1>(A, B); __syncthreads();
    radix8_stage<SIGN,  8, 1, 2>(B, A); __syncthreads();
    radix8_stage<SIGN, 64, 2, 0>(A, B); __syncthreads();
    radix4_stage<SIGN>(B, A);           __syncthreads();
}

// ---------------- table init ----------------
__global__ void init_tables() {
    __shared__ float2 sA[MP];
    __shared__ float2 sB[MP];
    const int tid = threadIdx.x;
    for (int k = tid; k < MP/2; k += blockDim.x) {
        double a = -2.0 * PI_D * (double)k / (double)MP;
        g_w2048[k] = make_float2((float)cos(a), (float)sin(a));
    }
    for (int m = tid; m < NP; m += blockDim.x) {
        double a = -2.0 * PI_D * (double)m / (double)NP;
        g_w542[m] = make_float2((float)cos(a), (float)sin(a));
        long tq = ((long)m * (long)m) % (2L * NP);
        double ca = -PI_D * (double)tq / (double)NP;
        g_chirp[m] = make_float2((float)cos(ca), (float)sin(ca));
    }
    __syncthreads();
    for (int i = tid; i < MP; i += blockDim.x) sA[i] = make_float2(0.f, 0.f);
    __syncthreads();
    for (int n = tid; n < NP; n += blockDim.x) {
        float2 c = g_chirp[n];
        float2 b = make_float2(c.x, -c.y);      // conj(chirp)
        sA[n] = b;
        if (n > 0) sA[MP - n] = b;
    }
    __syncthreads();
    fft2048_r8<1>(sA, sB);
    for (int i = tid; i < MP; i += blockDim.x) g_Bf[i] = sA[i];
}

// ---------------- edgetaper alpha vectors ----------------
__global__ void compute_v(const float* __restrict__ kk) {
    const int b = blockIdx.x;
    __shared__ float p0[KH], p1[KW], z0[KH], z1[KW];
    const int tid = threadIdx.x;
    const float* kb = kk + b * KH * KW;
    if (tid < KH) {
        float s = 0.f;
        for (int j = 0; j < KW; ++j) s += kb[tid*KW + j];
        p0[tid] = s;
    } else if (tid < KH + KW) {
        int j = tid - KH; float s = 0.f;
        for (int i = 0; i < KH; ++i) s += kb[i*KW + j];
        p1[j] = s;
    }
    __syncthreads();
    if (tid < KH) {
        float s = 0.f;
        for (int i = 0; i + tid < KH; ++i) s += p0[i] * p0[i + tid];
        z0[tid] = s;
    } else if (tid < KH + KW) {
        int m = tid - KH; float s = 0.f;
        for (int i = 0; i + m < KW; ++i) s += p1[i] * p1[i + m];
        z1[m] = s;
    }
    __syncthreads();
    const float inv0 = 1.f / z0[0];
    const float inv1 = 1.f / z1[0];
    for (int j = tid; j < NP; j += blockDim.x) {
        float a0, a1;
        if (j <= KH - 1)                a0 = z0[j];
        else if (j >= NP - 1)           a0 = z0[0];
        else if (j >= (NP-1)-(KH-1))    a0 = z0[(NP-1) - j];
        else                            a0 = 0.f;
        if (j <= KW - 1)                a1 = z1[j];
        else if (j >= NP - 1)           a1 = z1[0];
        else if (j >= (NP-1)-(KW-1))    a1 = z1[(NP-1) - j];
        else                            a1 = 0.f;
        g_v0[b*NP + j] = 1.f - a0 * inv0;
        g_v1[b*NP + j] = 1.f - a1 * inv1;
    }
}

// ---------------- Dk = psf2otf(k): two-step small DFT ----------------
__global__ void compute_Tk(const float* __restrict__ kk) {
    const int b = blockIdx.x, u = blockIdx.y;
    const int j = threadIdx.x;
    if (j >= KW) return;
    const float* kb = kk + b * KH * KW;
    float2 acc = make_float2(0.f, 0.f);
    for (int i = 0; i < KH; ++i) {
        int m = (u * (i - PH)) % NP; if (m < 0) m += NP;
        float2 w = g_w542[m];
        float kv = kb[i*KW + j];
        acc.x += kv * w.x;
        acc.y += kv * w.y;
    }
    g_Tk[(b*NP + u)*KW + j] = acc;
}

__global__ void compute_Dk() {
    const int u = blockIdx.x, b = blockIdx.y;
    __shared__ float2 Trow[KW];
    if (threadIdx.x < KW) Trow[threadIdx.x] = g_Tk[(b*NP + u)*KW + threadIdx.x];
    __syncthreads();
    for (int v = threadIdx.x; v < NP; v += blockDim.x) {
        const float2 wv = g_w542[v];
        int m0 = (v * PW) % NP;
        float2 w = make_float2(g_w542[m0].x, -g_w542[m0].y);  // w^{-v*PW}
        float2 acc = make_float2(0.f, 0.f);
#pragma unroll
        for (int j = 0; j < KW; ++j) {
            float2 t = Trow[j];
            acc.x += t.x*w.x - t.y*w.y;
            acc.y += t.x*w.y + t.y*w.x;
            w = cmul(w, wv);
        }
        g_Dk[(size_t)b*NP2 + (size_t)u*NP + v] = acc;
    }
}

// ---------------- Dg_sum ----------------
__global__ void compute_DgSum(const float* __restrict__ filters) {
    const int u = blockIdx.x, c = blockIdx.y;
    __shared__ float fl[NF*FS*FS];
    for (int i = threadIdx.x; i < NF*FS*FS; i += blockDim.x) {
        int f = i / (FS*FS);
        int r = i % (FS*FS);
        fl[i] = filters[(f*CC + c)*FS*FS + r];
    }
    __syncthreads();
    for (int v = threadIdx.x; v < NP; v += blockDim.x) {
        float sum = 0.f;
        for (int f = 0; f < NF; ++f) {
            float2 acc = make_float2(0.f, 0.f);
            for (int i = 0; i < FS; ++i)
                for (int j = 0; j < FS; ++j) {
                    int m = (u*(i-1) + v*(j-1)) % NP; if (m < 0) m += NP;
                    float2 w = g_w542[m];
                    float kv = fl[f*9 + i*3 + j];
                    acc.x += kv * w.x;
                    acc.y += kv * w.y;
                }
            sum += acc.x*acc.x + acc.y*acc.y;
        }
        g_DgSum[(size_t)c*NP2 + (size_t)u*NP + v] = sum;
    }
}

// ---------------- edge-replicate pad ----------------
__global__ void pad_edge(const float* __restrict__ y) {
    const int idx = blockIdx.x * blockDim.x + threadIdx.x;
    if (idx >= NIMG*NP2) return;
    const int w = idx % NP;
    const int h = (idx / NP) % NP;
    const int img = idx / NP2;
    const int sh = min(max(h - PH, 0), HIN - 1);
    const int sw = min(max(w - PW, 0), WIN - 1);
    g_Xr[idx] = y[(size_t)img*HIN*WIN + sh*WIN + sw];
}

// ---------------- fused Bluestein FFT pass (2 rows per block) ----------------
// LM: load mode. INV: inverse direction (conj trick + 1/NP scale).
// SRCSEL: 1 = g_T, 2 = g_U (for complex loads).
// DSTSEL: 0 = g_T, 1 = g_U (complex), 2 = g_Fr (real), 3 = out (real).
template<int LM, int INV, int SRCSEL, int DSTSEL>
__global__ void __launch_bounds__(256) fft_pass(float* __restrict__ out,
                                                const float* __restrict__ lam) {
    __shared__ float2 sA[MP];
    __shared__ float2 sB[MP];
    __shared__ float2 sR[NP];
    const int tid = threadIdx.x;
    const int r0  = blockIdx.x * 2;
    const int img = blockIdx.y;
    const int b   = img / CC;
    const int cch = img % CC;

#pragma unroll 1
    for (int half = 0; half < 2; ++half) {
        const int row = r0 + half;
        const size_t rowoff = ((size_t)img * NP + row) * NP;

        // ---- load + fused pointwise op + chirp ----
        if (LM == LM_X) {
            const float* s = g_Xr + rowoff;
            for (int i = tid; i < MP; i += 256) {
                float2 v = make_float2(0.f, 0.f);
                if (i < NP) {
                    float xr = s[i];
                    float2 ch = g_chirp[i];
                    v = make_float2(xr*ch.x, xr*ch.y);
                }
                sA[i] = v;
            }
        } else if (LM == LM_BLEND) {
            float* s = g_Xr + rowoff;
            const float* f = g_Fr + rowoff;
            const float av0 = g_v0[b*NP + row];
            for (int i = tid; i < MP; i += 256) {
                float2 v = make_float2(0.f, 0.f);
                if (i < NP) {
                    float a  = av0 * g_v1[b*NP + i];
                    float xn = a * s[i] + (1.f - a) * f[i];
                    s[i] = xn;                              // write back X_new
                    float2 ch = g_chirp[i];
                    v = make_float2(xn*ch.x, xn*ch.y);
                }
                sA[i] = v;
            }
        } else {
            const float2* s = ((SRCSEL == 1) ? g_T : g_U) + rowoff;
            const float el = (LM == LM_WI) ? expf(lam[0]) : 0.f;
            for (int i = tid; i < MP; i += 256) {
                float2 v = make_float2(0.f, 0.f);
                if (i < NP) {
                    float2 z = s[i];
                    if (LM == LM_DK) {
                        float2 dk = g_Dk[(size_t)(b*NP + row)*NP + i];
                        z = cmul(z, dk);
                    } else if (LM == LM_WI) {
                        float2 dk = g_Dk[(size_t)(b*NP + row)*NP + i];
                        float om = 1.f / (dk.x*dk.x + dk.y*dk.y
                                          + el * g_DgSum[(size_t)(cch*NP + row)*NP + i]);
                        z = make_float2((dk.x*z.x + dk.y*z.y) * om,
                                        (dk.x*z.y - dk.y*z.x) * om);
                    }
                    if (INV) z.y = -z.y;                    // conj trick
                    v = cmul(z, g_chirp[i]);
                }
                sA[i] = v;
            }
        }
        __syncthreads();

        // ---- Bluestein: fwd 2048-FFT, * Bf, inv 2048-FFT ----
        fft2048_r8<1>(sA, sB);
        for (int i = tid; i < MP; i += 256) sA[i] = cmul(sA[i], g_Bf[i]);
        __syncthreads();
        fft2048_r8<-1>(sA, sB);

        // ---- finalize + transposed paired store ----
        const float sc = INV ? (1.f / ((float)MP * (float)NP)) : (1.f / (float)MP);
        if (half == 0) {
            for (int k = tid; k < NP; k += 256) {
                float2 v = cmul(sA[k], g_chirp[k]);
                v.x *= sc;
                v.y = INV ? -v.y * sc : v.y * sc;
                sR[k] = v;                                  // same thread re-reads later
            }
        } else {
            if (DSTSEL == 0 || DSTSEL == 1) {
                float2* d = ((DSTSEL == 0) ? g_T : g_U) + (size_t)img * NP2;
                for (int k = tid; k < NP; k += 256) {
                    float2 v = cmul(sA[k], g_chirp[k]);
                    v.x *= sc;
                    v.y = INV ? -v.y * sc : v.y * sc;
                    float2 u0 = sR[k];
                    *reinterpret_cast<float4*>(&d[(size_t)k*NP + r0]) =
                        make_float4(u0.x, u0.y, v.x, v.y);
                }
            } else {
                float* d = (DSTSEL == 2) ? (g_Fr + (size_t)img * NP2)
                                         : (out  + (size_t)img * NP2);
                for (int k = tid; k < NP; k += 256) {
                    float vx = (sA[k].x * g_chirp[k].x - sA[k].y * g_chirp[k].y) * sc;
                    *reinterpret_cast<float2*>(&d[(size_t)k*NP + r0]) =
                        make_float2(sR[k].x, vx);
                }
            }
        }
        __syncthreads();
    }
}

// ---------------- launch ----------------
extern "C" void kernel_launch(void* const* d_in, const int* in_sizes, int n_in,
                              void* d_out, int out_size) {
    const float* y       = (const float*)d_in[0];
    const float* kk      = (const float*)d_in[1];
    const float* lam     = (const float*)d_in[2];
    const float* filters = (const float*)d_in[3];
    float* out = (float*)d_out;

    init_tables<<<1, 256>>>();
    compute_v<<<BB, 64>>>(kk);
    compute_Tk<<<dim3(BB, NP), 32>>>(kk);
    compute_Dk<<<dim3(NP, BB), 256>>>();
    compute_DgSum<<<dim3(NP, CC), 256>>>(filters);

    const int n  = NIMG * NP2;
    pad_edge<<<(n + 255) / 256, 256>>>(y);

    const dim3 pg(NP / 2, NIMG);

    // iteration 1 (no blend on first forward pass)
    fft_pass<LM_X,     0, 0, 0><<<pg, 256>>>(out, lam);   // X  -> T   (fwd rows)
    fft_pass<LM_C,     0, 1, 1><<<pg, 256>>>(out, lam);   // T  -> U   (fwd cols)
    fft_pass<LM_DK,    1, 2, 0><<<pg, 256>>>(out, lam);   // U*Dk -> T (inv)
    fft_pass<LM_C,     1, 1, 2><<<pg, 256>>>(out, lam);   // T  -> Fr  (inv, real)

    // iterations 2, 3 (blend fused into forward load)
    for (int it = 0; it < 2; ++it) {
        fft_pass<LM_BLEND, 0, 0, 0><<<pg, 256>>>(out, lam);
        fft_pass<LM_C,     0, 1, 1><<<pg, 256>>>(out, lam);
        fft_pass<LM_DK,    1, 2, 0><<<pg, 256>>>(out, lam);
        fft_pass<LM_C,     1, 1, 2><<<pg, 256>>>(out, lam);
    }

    // final: blend, fft2, Wiener, ifft2 -> out
    fft_pass<LM_BLEND, 0, 0, 0><<<pg, 256>>>(out, lam);
    fft_pass<LM_C,     0, 1, 1><<<pg, 256>>>(out, lam);
    fft_pass<LM_WI,    1, 2, 0><<<pg, 256>>>(out, lam);
    fft_pass<LM_C,     1, 1, 3><<<pg, 256>>>(out, lam);
}